// round 9
// baseline (speedup 1.0000x reference)
#include <cuda_runtime.h>
#include <math_constants.h>

#define N_POINTS 50000
#define CHANNELS 64
#define NREP 4            // cursor replicas (contention privatization)
#define CAP_SUB 32        // per-replica sub-bucket capacity (counts ~Poisson(8))
#define CAP (NREP * CAP_SUB)   // 128 entries per point, row = 512B
#define OVF_CAP (1 << 20) // overflow list capacity (expected usage: 0)

// Static scratch (no allocations). __device__ globals are zero-initialized at
// module load; segmax_kernel restores all counters to zero after consuming
// them, so the zero-invariant holds for every call and graph replay.
// Replicas live in SEPARATE arrays so a point's 4 counters map to different
// L2 slices -> the per-address atomic serialization parallelizes 4x.
__device__ int d_cursor0[N_POINTS];
__device__ int d_cursor1[N_POINTS];
__device__ int d_cursor2[N_POINTS];
__device__ int d_cursor3[N_POINTS];
__device__ int d_bucket[N_POINTS * CAP];   // 25.6 MB; sub r at [p*CAP + r*32, +32)
__device__ int d_ovf_count;
__device__ int d_ovf_list[OVF_CAP];        // edge ids that exceeded CAP_SUB
__device__ int d_done;                     // K3 block-arrival counter

__device__ __forceinline__ int* cursor_ptr(int r, int p) {
    switch (r & 3) {
        case 0:  return &d_cursor0[p];
        case 1:  return &d_cursor1[p];
        case 2:  return &d_cursor2[p];
        default: return &d_cursor3[p];
    }
}

// ---------------------------------------------------------------------------
// K2: bucket-build with privatized cursors. Four edges per thread (two int4
// index loads); replica = edge & 3, so a point's ~32 incoming edges spread
// ~8 per replica -> 4x less same-address atomic serialization at the LTS.
// ---------------------------------------------------------------------------
__device__ __forceinline__ void bucket_one(int e, int o_idx, int i_idx) {
    int r = e & 3;
    int pos = atomicAdd(cursor_ptr(r, o_idx), 1);
    if (pos < CAP_SUB) {
        d_bucket[o_idx * CAP + r * CAP_SUB + pos] = i_idx;
    } else {
        int op = atomicAdd(&d_ovf_count, 1);
        if (op < OVF_CAP) d_ovf_list[op] = e;
    }
}

__global__ void bucket_kernel(const int* __restrict__ idx, int n_edges) {
    int t = blockIdx.x * blockDim.x + threadIdx.x;
    int e0 = t * 4;
    if (e0 + 4 <= n_edges) {
        int4 a = __ldg(reinterpret_cast<const int4*>(idx) + 2 * t);
        int4 b = __ldg(reinterpret_cast<const int4*>(idx) + 2 * t + 1);
        bucket_one(e0,     a.x, a.y);
        bucket_one(e0 + 1, a.z, a.w);
        bucket_one(e0 + 2, b.x, b.y);
        bucket_one(e0 + 3, b.z, b.w);
    } else {
        for (int e = e0; e < n_edges; e++) {
            int2 pr = __ldg(reinterpret_cast<const int2*>(idx) + e);
            bucket_one(e, pr.x, pr.y);
        }
    }
}

// ---------------------------------------------------------------------------
// K3: dense segment-max (R7's proven 35.6us body, adapted to 4 sub-buckets).
// 16 lanes per point, one float4 (4 channels) per lane; coalesced 256B row
// gathers from the L2-resident feature table; max in registers; write-only
// store (covers empty segments -> -inf). Overflow edges (expected: none)
// folded via a guarded scan of the compact list. Self-clean epilogue restores
// the zeroed counters.
// ---------------------------------------------------------------------------
__device__ __forceinline__ float4 max4(float4 a, float4 b) {
    return make_float4(fmaxf(a.x, b.x), fmaxf(a.y, b.y),
                       fmaxf(a.z, b.z), fmaxf(a.w, b.w));
}

static_assert((N_POINTS * 16) % 256 == 0, "grid must be exact");

__global__ void __launch_bounds__(256)
segmax_kernel(const float* __restrict__ feat,
              const int* __restrict__ idx,
              float* __restrict__ out) {
    int t = blockIdx.x * blockDim.x + threadIdx.x;
    int p = t >> 4;
    int c4 = (t & 15) << 2;

    const float* featc = feat + c4;              // per-lane channel base

    int cnts[NREP];
    cnts[0] = d_cursor0[p];
    cnts[1] = d_cursor1[p];
    cnts[2] = d_cursor2[p];
    cnts[3] = d_cursor3[p];
    bool overflowed = false;

    float4 acc = make_float4(-CUDART_INF_F, -CUDART_INF_F, -CUDART_INF_F, -CUDART_INF_F);

    #pragma unroll
    for (int r = 0; r < NREP; r++) {
        int cnt = cnts[r];
        if (cnt > CAP_SUB) { cnt = CAP_SUB; overflowed = true; }
        const int* bkt = d_bucket + p * CAP + r * CAP_SUB;   // 128B-aligned

        int i = 0;
        // 4 indices per LDG (int4), 4 independent feature-row chains.
        for (; i + 4 <= cnt; i += 4) {
            int4 s = __ldg(reinterpret_cast<const int4*>(bkt + i));
            float4 v0 = __ldg(reinterpret_cast<const float4*>(featc + s.x * CHANNELS));
            float4 v1 = __ldg(reinterpret_cast<const float4*>(featc + s.y * CHANNELS));
            float4 v2 = __ldg(reinterpret_cast<const float4*>(featc + s.z * CHANNELS));
            float4 v3 = __ldg(reinterpret_cast<const float4*>(featc + s.w * CHANNELS));
            acc = max4(acc, max4(max4(v0, v1), max4(v2, v3)));
        }
        #pragma unroll 1
        for (; i < cnt; i++) {
            int s = __ldg(bkt + i);
            float4 v = __ldg(reinterpret_cast<const float4*>(featc + s * CHANNELS));
            acc = max4(acc, v);
        }
    }

    // Exactness guard: fold in any overflow edges targeting this point.
    // One L2-hot broadcast load; branch ~never taken.
    int ovf = d_ovf_count;
    if (ovf > 0 && overflowed) {
        if (ovf > OVF_CAP) ovf = OVF_CAP;
        #pragma unroll 1
        for (int j = 0; j < ovf; j++) {
            int e = d_ovf_list[j];
            int2 pr = __ldg(reinterpret_cast<const int2*>(idx) + e);
            if (pr.x == p) {
                float4 v = __ldg(reinterpret_cast<const float4*>(featc + pr.y * CHANNELS));
                acc = max4(acc, v);
            }
        }
    }

    *reinterpret_cast<float4*>(out + p * CHANNELS + c4) = acc;

    // --- Self-clean epilogue (replaces an init kernel) ---
    __syncthreads();                        // everyone in block done reading
    int lane16 = t & 15;
    if (lane16 < NREP) *cursor_ptr(lane16, p) = 0;   // lanes 0..3: one replica each
    if (threadIdx.x == 0) {
        __threadfence();
        int old = atomicAdd(&d_done, 1);
        if (old == gridDim.x - 1) {         // last block: all reads of
            d_ovf_count = 0;                // d_ovf_count already happened
            d_done = 0;
        }
    }
}

extern "C" void kernel_launch(void* const* d_in, const int* in_sizes, int n_in,
                              void* d_out, int out_size) {
    const float* feat = (const float*)d_in[0];   // [N_POINTS, 64] f32
    const int* idx = (const int*)d_in[1];        // [N_EDGES, 2] i32
    float* out = (float*)d_out;                  // [N_POINTS, 64] f32

    int n_edges = in_sizes[1] / 2;

    // K2: bucket build (4 edges / thread, replicated cursors)
    int nt4 = (n_edges + 3) / 4;
    bucket_kernel<<<(nt4 + 255) / 256, 256>>>(idx, n_edges);

    // K3: dense per-point max (16 lanes/point) + self-clean
    segmax_kernel<<<(N_POINTS * 16) / 256, 256>>>(feat, idx, out);
}

// round 10
// speedup vs baseline: 1.1835x; 1.1835x over previous
#include <cuda_runtime.h>
#include <math_constants.h>

#define N_POINTS 50000
#define CHANNELS 64
#define CAP 128           // bucket capacity per point; counts ~Poisson(32), max ~66
#define OVF_CAP (1 << 20) // overflow list capacity (expected usage: 0)

// Static scratch (no allocations). __device__ globals are zero-initialized at
// module load; segmax_kernel restores all counters to zero after consuming
// them, so the zero-invariant holds for every call and graph replay.
__device__ int d_cursor[N_POINTS];
__device__ int d_bucket[N_POINTS * CAP];   // 25.6 MB, 512B-aligned contiguous rows
__device__ int d_ovf_count;
__device__ int d_ovf_list[OVF_CAP];        // edge ids that exceeded CAP
__device__ int d_done;                     // K3 block-arrival counter

// ---------------------------------------------------------------------------
// K2: bucket-build. ONE edge per thread (int2 index load): K2 is bound by
// hiding the ~318-cycle atomic-return latency, so maximize resident warps
// rather than per-thread ILP (4 edges/thread measured ~5us slower).
// ---------------------------------------------------------------------------
__global__ void bucket_kernel(const int* __restrict__ idx, int n_edges) {
    int e = blockIdx.x * blockDim.x + threadIdx.x;
    if (e >= n_edges) return;
    int2 pr = __ldg(reinterpret_cast<const int2*>(idx) + e);
    int pos = atomicAdd(&d_cursor[pr.x], 1);
    if (pos < CAP) {
        d_bucket[pr.x * CAP + pos] = pr.y;
    } else {
        int op = atomicAdd(&d_ovf_count, 1);
        if (op < OVF_CAP) d_ovf_list[op] = e;
    }
}

// ---------------------------------------------------------------------------
// K3: dense segment-max — byte-for-byte the measured-35.6us R7 body.
// 16 lanes per point, one float4 (4 channels) per lane; coalesced 256B row
// gathers from the L2-resident feature table (~97% of the LTS cap); max in
// registers; write-only store (covers empty segments -> -inf). Overflow edges
// (expected: none) folded via a guarded scan of the compact list.
// Self-clean epilogue restores the zeroed counters (replaces an init kernel).
// ---------------------------------------------------------------------------
__device__ __forceinline__ float4 max4(float4 a, float4 b) {
    return make_float4(fmaxf(a.x, b.x), fmaxf(a.y, b.y),
                       fmaxf(a.z, b.z), fmaxf(a.w, b.w));
}

static_assert((N_POINTS * 16) % 256 == 0, "grid must be exact");

__global__ void segmax_kernel(const float* __restrict__ feat,
                              const int* __restrict__ idx,
                              float* __restrict__ out) {
    int t = blockIdx.x * blockDim.x + threadIdx.x;
    int p = t >> 4;
    int c4 = (t & 15) << 2;

    int cnt = d_cursor[p];
    if (cnt > CAP) cnt = CAP;
    const int* bkt = d_bucket + p * CAP;   // 512B-aligned

    float4 acc = make_float4(-CUDART_INF_F, -CUDART_INF_F, -CUDART_INF_F, -CUDART_INF_F);

    int i = 0;
    // 4 indices per LDG (int4), 4 independent feature-row chains in flight.
    for (; i + 4 <= cnt; i += 4) {
        int4 s = __ldg(reinterpret_cast<const int4*>(bkt + i));
        float4 v0 = *reinterpret_cast<const float4*>(feat + (long long)s.x * CHANNELS + c4);
        float4 v1 = *reinterpret_cast<const float4*>(feat + (long long)s.y * CHANNELS + c4);
        float4 v2 = *reinterpret_cast<const float4*>(feat + (long long)s.z * CHANNELS + c4);
        float4 v3 = *reinterpret_cast<const float4*>(feat + (long long)s.w * CHANNELS + c4);
        acc = max4(acc, max4(max4(v0, v1), max4(v2, v3)));
    }
    for (; i < cnt; i++) {
        int s = __ldg(bkt + i);
        float4 v = *reinterpret_cast<const float4*>(feat + (long long)s * CHANNELS + c4);
        acc = max4(acc, v);
    }

    // Exactness guard: fold in any overflow edges targeting this point.
    // One L2-hot broadcast load; branch ~never taken.
    int ovf = d_ovf_count;
    if (ovf > 0) {
        if (ovf > OVF_CAP) ovf = OVF_CAP;
        for (int j = 0; j < ovf; j++) {
            int e = d_ovf_list[j];
            int2 pr = __ldg(reinterpret_cast<const int2*>(idx) + e);
            if (pr.x == p) {
                float4 v = *reinterpret_cast<const float4*>(feat + (long long)pr.y * CHANNELS + c4);
                acc = max4(acc, v);
            }
        }
    }

    *reinterpret_cast<float4*>(out + p * CHANNELS + c4) = acc;

    // --- Self-clean epilogue (replaces an init kernel) ---
    __syncthreads();                       // everyone in block done reading
    if ((t & 15) == 0) d_cursor[p] = 0;    // one lane per point
    if (threadIdx.x == 0) {
        __threadfence();
        int old = atomicAdd(&d_done, 1);
        if (old == gridDim.x - 1) {        // last block: all reads of
            d_ovf_count = 0;               // d_ovf_count already happened
            d_done = 0;
        }
    }
}

extern "C" void kernel_launch(void* const* d_in, const int* in_sizes, int n_in,
                              void* d_out, int out_size) {
    const float* feat = (const float*)d_in[0];   // [N_POINTS, 64] f32
    const int* idx = (const int*)d_in[1];        // [N_EDGES, 2] i32
    float* out = (float*)d_out;                  // [N_POINTS, 64] f32

    int n_edges = in_sizes[1] / 2;

    // K2: bucket build, 1 edge / thread (max latency hiding)
    bucket_kernel<<<(n_edges + 255) / 256, 256>>>(idx, n_edges);

    // K3: dense per-point max (16 lanes/point) + self-clean
    segmax_kernel<<<(N_POINTS * 16) / 256, 256>>>(feat, idx, out);
}